// round 12
// baseline (speedup 1.0000x reference)
#include <cuda_runtime.h>

// SiteWiseLSTM on GB300 (sm_103a) — round 8
// tcgen05 is unavailable (harness compiles PTX at target sm_103, no 'a').
// This round: occupancy. Same algorithm/SMEM as the 5947us kernel but
// TH=512 (16 warps -> 4 warps/SMSP, was 2) with a half tile per thread:
//   2 units x 4 gates x 4 samples  (16 fma.rn.f32x2 per k-iter, 32 acc regs)
// Per-SM FMA/MUFU work is conserved; doubled warp pool hides LDS/MUFU latency.

#define TH      512
#define MM      64      // samples per block
#define HID     64
#define GATES   256
#define LL      168
#define HOR     24
#define SS      512
#define NB      256     // 16384 / MM
#define HS      68      // h row stride in floats

typedef unsigned long long u64t;

__device__ __forceinline__ u64t pk2(float a, float b) {
    u64t r;
    asm("mov.b64 %0, {%1, %2};" : "=l"(r) : "f"(a), "f"(b));
    return r;
}
__device__ __forceinline__ void upk2(u64t v, float& a, float& b) {
    asm("mov.b64 {%0, %1}, %2;" : "=f"(a), "=f"(b) : "l"(v));
}
__device__ __forceinline__ void fma2(u64t& d, u64t a, u64t b) {
    asm("fma.rn.f32x2 %0, %1, %2, %0;" : "+l"(d) : "l"(a), "l"(b));
}
__device__ __forceinline__ float tanha(float x) {
    float y;
    asm("tanh.approx.f32 %0, %1;" : "=f"(y) : "f"(x));
    return y;
}
__device__ __forceinline__ float sigf(float x) {
    return fmaf(0.5f, tanha(0.5f * x), 0.5f);
}

// acc[u][g][p] += W[k][8up+4u+g] * h[k][ms..ms+3], k = 0..63.
// Ws pre-offset by up*8; hb pre-offset by ms.
__device__ __forceinline__ void matG(const float* __restrict__ Ws,
                                     const float* __restrict__ hb,
                                     u64t acc[2][4][2]) {
#pragma unroll 4
    for (int k = 0; k < HID; ++k) {
        float4 wA = *(const float4*)(Ws + k * GATES);      // unit0 gates ifgo
        float4 wB = *(const float4*)(Ws + k * GATES + 4);  // unit1 gates ifgo
        ulonglong2 hA = *(const ulonglong2*)(hb + k * HS); // 4 samples
        u64t w2;
        w2 = pk2(wA.x, wA.x); fma2(acc[0][0][0], hA.x, w2); fma2(acc[0][0][1], hA.y, w2);
        w2 = pk2(wA.y, wA.y); fma2(acc[0][1][0], hA.x, w2); fma2(acc[0][1][1], hA.y, w2);
        w2 = pk2(wA.z, wA.z); fma2(acc[0][2][0], hA.x, w2); fma2(acc[0][2][1], hA.y, w2);
        w2 = pk2(wA.w, wA.w); fma2(acc[0][3][0], hA.x, w2); fma2(acc[0][3][1], hA.y, w2);
        w2 = pk2(wB.x, wB.x); fma2(acc[1][0][0], hA.x, w2); fma2(acc[1][0][1], hA.y, w2);
        w2 = pk2(wB.y, wB.y); fma2(acc[1][1][0], hA.x, w2); fma2(acc[1][1][1], hA.y, w2);
        w2 = pk2(wB.z, wB.z); fma2(acc[1][2][0], hA.x, w2); fma2(acc[1][2][1], hA.y, w2);
        w2 = pk2(wB.w, wB.w); fma2(acc[1][3][0], hA.x, w2); fma2(acc[1][3][1], hA.y, w2);
    }
}

__device__ __forceinline__ void addx(u64t acc[2][4][2], float4 xA,
                                     const float wg[2][4]) {
    u64t xp0 = pk2(xA.x, xA.y), xp1 = pk2(xA.z, xA.w);
#pragma unroll
    for (int u = 0; u < 2; ++u)
#pragma unroll
        for (int g = 0; g < 4; ++g) {
            u64t w2 = pk2(wg[u][g], wg[u][g]);
            fma2(acc[u][g][0], xp0, w2); fma2(acc[u][g][1], xp1, w2);
        }
}

__device__ __forceinline__ void initacc(u64t acc[2][4][2], const float bg[2][4]) {
#pragma unroll
    for (int u = 0; u < 2; ++u)
#pragma unroll
        for (int g = 0; g < 4; ++g) {
            u64t bb = pk2(bg[u][g], bg[u][g]);
            acc[u][g][0] = bb; acc[u][g][1] = bb;
        }
}

// LSTM cell for 2 units x 4 samples; c[8]; one STS.128 per unit at rowp+u*HS+ms.
__device__ __forceinline__ void cellstore2(u64t acc[2][4][2], float* c,
                                           float* __restrict__ rowp, int ms) {
#pragma unroll
    for (int u = 0; u < 2; ++u) {
        float hv[4];
#pragma unroll
        for (int p = 0; p < 2; ++p) {
            float i0, i1, f0, f1, g0, g1, o0, o1;
            upk2(acc[u][0][p], i0, i1);
            upk2(acc[u][1][p], f0, f1);
            upk2(acc[u][2][p], g0, g1);
            upk2(acc[u][3][p], o0, o1);
            int ci = u * 4 + p * 2;
            float nc0 = sigf(f0) * c[ci]     + sigf(i0) * tanha(g0);
            float nc1 = sigf(f1) * c[ci + 1] + sigf(i1) * tanha(g1);
            c[ci] = nc0; c[ci + 1] = nc1;
            hv[p * 2]     = sigf(o0) * tanha(nc0);
            hv[p * 2 + 1] = sigf(o1) * tanha(nc1);
        }
        *(float4*)(rowp + u * HS + ms) = make_float4(hv[0], hv[1], hv[2], hv[3]);
    }
}

__global__ void __launch_bounds__(TH, 1)
sitewise_lstm_kernel(const float* __restrict__ X,
                     const float* __restrict__ Wih0, const float* __restrict__ Whh0,
                     const float* __restrict__ bih0, const float* __restrict__ bhh0,
                     const float* __restrict__ Wih1, const float* __restrict__ Whh1,
                     const float* __restrict__ bih1, const float* __restrict__ bhh1,
                     const float* __restrict__ Wcih, const float* __restrict__ Wchh,
                     const float* __restrict__ bcih, const float* __restrict__ bchh,
                     const float* __restrict__ Wout, const float* __restrict__ bout,
                     float* __restrict__ out) {
    extern __shared__ float sm[];
    float* W0s  = sm;                      // 64 k  x 256  (Whh0; later Wchh)
    float* W1s  = W0s + HID * GATES;       // 128 k x 256  ([Wih1;Whh1])
    float* hbuf = W1s + 2 * HID * GATES;   // 128 rows x HS (0-63 h0, 64-127 h1)
    float* xcur = hbuf + 2 * HID * HS;     // 64
    float* wouts = xcur + MM;              // 64

    const int tid = threadIdx.x;
    const int mg  = tid & 15;              // sample group (0..15), lanes 0-15/16-31
    const int up  = tid >> 4;              // unit pair (0..31)
    const int ms  = mg * 4;
    const int w8  = up * 8;

    const int n0 = blockIdx.x * MM;
    const int b  = n0 >> 9;
    const int s0 = n0 & (SS - 1);
    const long xrow = (long)b * LL * SS + s0;

    // ---- stage weights (gate-interleaved, k-major): Wint[k][u*4+g] ----
    for (int idx = tid; idx < GATES * HID; idx += TH) {
        int jj = idx >> 6, k = idx & 63;
        int g = jj >> 6, u = jj & 63;
        int d = k * GATES + u * 4 + g;
        W0s[d] = Whh0[idx];
        W1s[d] = Wih1[idx];
        W1s[(HID + k) * GATES + u * 4 + g] = Whh1[idx];
    }
    for (int idx = tid; idx < 2 * HID * HS; idx += TH) hbuf[idx] = 0.f;
    if (tid < HID) wouts[tid] = Wout[tid];

    float w0g[2][4], b0g[2][4], b1g[2][4];
#pragma unroll
    for (int u = 0; u < 2; ++u)
#pragma unroll
        for (int g = 0; g < 4; ++g) {
            int row = g * 64 + 2 * up + u;
            w0g[u][g] = Wih0[row];
            b0g[u][g] = bih0[row] + bhh0[row];
            b1g[u][g] = bih1[row] + bhh1[row];
        }
    float c0[8], c1[8];
#pragma unroll
    for (int i = 0; i < 8; ++i) { c0[i] = 0.f; c1[i] = 0.f; }

    float* rowp0 = hbuf + (2 * up) * HS;
    float* rowp1 = hbuf + (HID + 2 * up) * HS;

    __syncthreads();

    // ================= encoder (2 barriers per step) =================
    for (int t = 0; t < LL; ++t) {
        float4 xA = __ldg((const float4*)(X + xrow + (long)t * SS + ms));

        u64t acc[2][4][2];
        // ---- layer 0: b0 + Whh0.h0_old + x*wih0 ----
        initacc(acc, b0g);
        matG(W0s + w8, hbuf + ms, acc);                     // reads h0_old
        addx(acc, xA, w0g);
        __syncthreads();                                    // bar1: h0_old reads done

        cellstore2(acc, c0, rowp0, ms);                     // writes h0_new (h0 rows)
        initacc(acc, b1g);
        matG(W1s + HID * GATES + w8, hbuf + HID * HS + ms, acc); // Whh1 . h1_old
        __syncthreads();                                    // bar2: h0_new published,
                                                            //       h1_old reads done
        matG(W1s + w8, hbuf + ms, acc);                     // Wih1 . h0_new
        cellstore2(acc, c1, rowp1, ms);                     // writes h1_new (h1 rows)
    }

    // ================= decoder =================
    __syncthreads();                                        // h1_new visible
    for (int idx = tid; idx < GATES * HID; idx += TH) {     // W0s <- Wchh
        int jj = idx >> 6, k = idx & 63;
        int g = jj >> 6, u = jj & 63;
        W0s[k * GATES + u * 4 + g] = Wchh[idx];
    }
    float wcg[2][4], bcg[2][4];
#pragma unroll
    for (int u = 0; u < 2; ++u)
#pragma unroll
        for (int g = 0; g < 4; ++g) {
            int row = g * 64 + 2 * up + u;
            wcg[u][g] = Wcih[row];
            bcg[u][g] = bcih[row] + bchh[row];
        }
    if (tid < MM) xcur[tid] = X[xrow + (long)(LL - 1) * SS + tid];
    const float bo = bout[0];
    __syncthreads();

    for (int d = 0; d < HOR; ++d) {
        u64t acc[2][4][2];
        initacc(acc, bcg);
        float4 xA = *(const float4*)(xcur + ms);
        matG(W0s + w8, hbuf + HID * HS + ms, acc);          // h1_old
        addx(acc, xA, wcg);
        __syncthreads();                                    // h1_old + xcur reads done
        cellstore2(acc, c1, rowp1, ms);                     // h1_new
        __syncthreads();                                    // h1_new visible

        if (tid < MM) {
            float y = bo;
#pragma unroll 8
            for (int k = 0; k < HID; ++k)
                y = fmaf(wouts[k], hbuf[(HID + k) * HS + tid], y);
            out[((long)(b * HOR + d)) * SS + s0 + tid] = y;
            xcur[tid] = y;
        }
        __syncthreads();                                    // xcur visible
    }
}

extern "C" void kernel_launch(void* const* d_in, const int* in_sizes, int n_in,
                              void* d_out, int out_size) {
    const float* X    = (const float*)d_in[0];
    const float* Wih0 = (const float*)d_in[1];
    const float* Whh0 = (const float*)d_in[2];
    const float* bih0 = (const float*)d_in[3];
    const float* bhh0 = (const float*)d_in[4];
    const float* Wih1 = (const float*)d_in[5];
    const float* Whh1 = (const float*)d_in[6];
    const float* bih1 = (const float*)d_in[7];
    const float* bhh1 = (const float*)d_in[8];
    const float* Wcih = (const float*)d_in[9];
    const float* Wchh = (const float*)d_in[10];
    const float* bcih = (const float*)d_in[11];
    const float* bchh = (const float*)d_in[12];
    const float* Wout = (const float*)d_in[13];
    const float* bout = (const float*)d_in[14];

    const int smem_floats = HID * GATES
                          + 2 * HID * GATES
                          + 2 * HID * HS
                          + MM
                          + HID;
    const int smem_bytes = smem_floats * (int)sizeof(float);

    cudaFuncSetAttribute(sitewise_lstm_kernel,
                         cudaFuncAttributeMaxDynamicSharedMemorySize, smem_bytes);

    sitewise_lstm_kernel<<<NB, TH, smem_bytes>>>(
        X, Wih0, Whh0, bih0, bhh0, Wih1, Whh1, bih1, bhh1,
        Wcih, Wchh, bcih, bchh, Wout, bout, (float*)d_out);
}

// round 13
// speedup vs baseline: 2.3537x; 2.3537x over previous
#include <cuda_runtime.h>
#include <cuda_fp16.h>
#include <cstdint>

// SiteWiseLSTM (sm_103a) — round 9: mma.sync (HMMA) fp16 split-precision.
// D[gates=256, samples=64] = W[256,64] @ h[64,64], m16n8k16 tiles, fp32 accum.
// 3-pass split: Whi.hhi + Wlo.hhi + Whi.hlo  (residual ~2^-22).
// Gate-row permutation r = 32*(u>>3) + 8*e + (u&7): warp j owns m-tiles 2j,2j+1
// so thread (g=lane>>2, tg=lane&3) accumulates ALL 4 gates of unit u=8j+g for
// samples 8nt+2tg,+1 -> in-register LSTM cell, c state in regs.
// W_hi fragments persistent in registers; W_lo + h (hi/lo, double-buffered) in
// SMEM with 144B row stride (bank-conflict-free b32 fragment loads).

#define TH   256
#define MM   64
#define HID  64
#define LL   168
#define HOR  24
#define SS   512
#define NB   256
#define HSW  72          // row stride in halves (144B)

// SMEM byte offsets
#define WLO0  0          // [256][72] half : Whh0 lo (decoder: Wchh lo)
#define WLO1  36864      // Wih1 lo
#define WLO2  73728      // Whh1 lo
#define HB    110592     // 8 x [64][72] half h arrays (73728 B); also init temp
#define XB    184320     // float[2][64]
#define WOUTS 184832     // float[64]
#define SMEMB 185344

__device__ __forceinline__ uint32_t lh2(const __half* p) {
    return *(const uint32_t*)p;
}
__device__ __forceinline__ float tanha(float x) {
    float y;
    asm("tanh.approx.f32 %0, %1;" : "=f"(y) : "f"(x));
    return y;
}
__device__ __forceinline__ float sigf(float x) {
    return fmaf(0.5f, tanha(0.5f * x), 0.5f);
}
__device__ __forceinline__ void mma16816(float* d, uint32_t a0, uint32_t a1,
                                         uint32_t a2, uint32_t a3,
                                         uint32_t b0, uint32_t b1) {
    asm volatile(
        "mma.sync.aligned.m16n8k16.row.col.f32.f16.f16.f32 "
        "{%0,%1,%2,%3}, {%4,%5,%6,%7}, {%8,%9}, {%0,%1,%2,%3};"
        : "+f"(d[0]), "+f"(d[1]), "+f"(d[2]), "+f"(d[3])
        : "r"(a0), "r"(a1), "r"(a2), "r"(a3), "r"(b0), "r"(b1));
}

// Stage fp32 W[256][64] (rows e*64+u) -> SMEM hi/lo fp16, permuted rows, 72-stride.
__device__ __forceinline__ void stageW(const float* __restrict__ W,
                                       __half* Hi, __half* Lo, int tid) {
    for (int idx = tid; idx < 256 * 64; idx += TH) {
        int row = idx >> 6, k = idx & 63;
        int e = row >> 6, u = row & 63;
        int r = ((u >> 3) << 5) + (e << 3) + (u & 7);
        float w = W[idx];
        __half hi = __float2half_rn(w);
        __half lo = __float2half_rn(w - __half2float(hi));
        Hi[r * HSW + k] = hi;
        Lo[r * HSW + k] = lo;
    }
}

__device__ __forceinline__ void loadfrags(const __half* Hi, uint32_t (&f)[2][4][4],
                                          int jr, int g, int tg) {
#pragma unroll
    for (int m = 0; m < 2; ++m)
#pragma unroll
        for (int kt = 0; kt < 4; ++kt) {
            int r0 = jr + 16 * m + g, r1 = r0 + 8, kb = 16 * kt + 2 * tg;
            f[m][kt][0] = lh2(Hi + r0 * HSW + kb);
            f[m][kt][1] = lh2(Hi + r1 * HSW + kb);
            f[m][kt][2] = lh2(Hi + r0 * HSW + kb + 8);
            f[m][kt][3] = lh2(Hi + r1 * HSW + kb + 8);
        }
}

// One matG: d += (Whi+Wlo).(Bhi) + Whi.(Blo), all nt/k tiles.
__device__ __forceinline__ void matphase(const uint32_t (&ahi)[2][4][4],
                                         const __half* __restrict__ Alo,
                                         const __half* __restrict__ Bhi,
                                         const __half* __restrict__ Blo,
                                         float (&d)[8][2][4],
                                         int jr, int g, int tg) {
#pragma unroll
    for (int kt = 0; kt < 4; ++kt) {
        const int kb = 16 * kt + 2 * tg;
        uint32_t alo[2][4];
#pragma unroll
        for (int m = 0; m < 2; ++m) {
            int r0 = jr + 16 * m + g, r1 = r0 + 8;
            alo[m][0] = lh2(Alo + r0 * HSW + kb);
            alo[m][1] = lh2(Alo + r1 * HSW + kb);
            alo[m][2] = lh2(Alo + r0 * HSW + kb + 8);
            alo[m][3] = lh2(Alo + r1 * HSW + kb + 8);
        }
#pragma unroll
        for (int nt = 0; nt < 8; ++nt) {
            const __half* bp = Bhi + (8 * nt + g) * HSW + kb;
            uint32_t b0 = lh2(bp), b1 = lh2(bp + 8);
            mma16816(d[nt][0], ahi[0][kt][0], ahi[0][kt][1], ahi[0][kt][2], ahi[0][kt][3], b0, b1);
            mma16816(d[nt][1], ahi[1][kt][0], ahi[1][kt][1], ahi[1][kt][2], ahi[1][kt][3], b0, b1);
            mma16816(d[nt][0], alo[0][0], alo[0][1], alo[0][2], alo[0][3], b0, b1);
            mma16816(d[nt][1], alo[1][0], alo[1][1], alo[1][2], alo[1][3], b0, b1);
        }
#pragma unroll
        for (int nt = 0; nt < 8; ++nt) {
            const __half* bp = Blo + (8 * nt + g) * HSW + kb;
            uint32_t b0 = lh2(bp), b1 = lh2(bp + 8);
            mma16816(d[nt][0], ahi[0][kt][0], ahi[0][kt][1], ahi[0][kt][2], ahi[0][kt][3], b0, b1);
            mma16816(d[nt][1], ahi[1][kt][0], ahi[1][kt][1], ahi[1][kt][2], ahi[1][kt][3], b0, b1);
        }
    }
}

// Cell update + h writeback for the 16 (sample) cells this thread owns.
// d[nt][0][0,1]=i@s0,s1  d[nt][0][2,3]=f  d[nt][1][0,1]=g  d[nt][1][2,3]=o
__device__ __forceinline__ void epilayer(float (&d)[8][2][4], float* cst,
                                         const float* bc, const float* wc,
                                         const float* xb,
                                         __half* Hhi, __half* Hlo,
                                         int u, int tg) {
#pragma unroll
    for (int nt = 0; nt < 8; ++nt) {
        int s0 = 8 * nt + 2 * tg;
        float x0 = 0.f, x1 = 0.f;
        if (xb) { float2 xv = *(const float2*)(xb + s0); x0 = xv.x; x1 = xv.y; }
        float gi0 = d[nt][0][0] + bc[0], gi1 = d[nt][0][1] + bc[0];
        float gf0 = d[nt][0][2] + bc[1], gf1 = d[nt][0][3] + bc[1];
        float gg0 = d[nt][1][0] + bc[2], gg1 = d[nt][1][1] + bc[2];
        float go0 = d[nt][1][2] + bc[3], go1 = d[nt][1][3] + bc[3];
        if (xb) {
            gi0 = fmaf(wc[0], x0, gi0); gi1 = fmaf(wc[0], x1, gi1);
            gf0 = fmaf(wc[1], x0, gf0); gf1 = fmaf(wc[1], x1, gf1);
            gg0 = fmaf(wc[2], x0, gg0); gg1 = fmaf(wc[2], x1, gg1);
            go0 = fmaf(wc[3], x0, go0); go1 = fmaf(wc[3], x1, go1);
        }
        float nc0 = sigf(gf0) * cst[2 * nt]     + sigf(gi0) * tanha(gg0);
        float nc1 = sigf(gf1) * cst[2 * nt + 1] + sigf(gi1) * tanha(gg1);
        cst[2 * nt] = nc0; cst[2 * nt + 1] = nc1;
        float h0 = sigf(go0) * tanha(nc0);
        float h1 = sigf(go1) * tanha(nc1);
        __half hh0 = __float2half_rn(h0);
        __half hh1 = __float2half_rn(h1);
        Hhi[s0 * HSW + u] = hh0;
        Hlo[s0 * HSW + u] = __float2half_rn(h0 - __half2float(hh0));
        Hhi[(s0 + 1) * HSW + u] = hh1;
        Hlo[(s0 + 1) * HSW + u] = __float2half_rn(h1 - __half2float(hh1));
    }
}

__global__ void __launch_bounds__(TH, 1)
lstm_mma_kernel(const float* __restrict__ X,
                const float* __restrict__ Wih0, const float* __restrict__ Whh0,
                const float* __restrict__ bih0, const float* __restrict__ bhh0,
                const float* __restrict__ Wih1, const float* __restrict__ Whh1,
                const float* __restrict__ bih1, const float* __restrict__ bhh1,
                const float* __restrict__ Wcih, const float* __restrict__ Wchh,
                const float* __restrict__ bcih, const float* __restrict__ bchh,
                const float* __restrict__ Wout, const float* __restrict__ bout,
                float* __restrict__ out) {
    extern __shared__ char sm[];
    __half* wlo0 = (__half*)(sm + WLO0);
    __half* wlo1 = (__half*)(sm + WLO1);
    __half* wlo2 = (__half*)(sm + WLO2);
    __half* htmp = (__half*)(sm + HB);
    // h arrays: [buf] -> base
    __half* h0hi[2] = { (__half*)(sm + HB),          (__half*)(sm + HB + 9216) };
    __half* h0lo[2] = { (__half*)(sm + HB + 18432),  (__half*)(sm + HB + 27648) };
    __half* h1hi[2] = { (__half*)(sm + HB + 36864),  (__half*)(sm + HB + 46080) };
    __half* h1lo[2] = { (__half*)(sm + HB + 55296),  (__half*)(sm + HB + 64512) };
    float* xbuf  = (float*)(sm + XB);       // [2][64]
    float* wouts = (float*)(sm + WOUTS);    // [64]

    const int tid = threadIdx.x;
    const int lane = tid & 31;
    const int j = tid >> 5;           // warp = m-pair
    const int g = lane >> 2;
    const int tg = lane & 3;
    const int jr = 32 * j;
    const int u = 8 * j + g;          // unit owned by this thread

    const int n0 = blockIdx.x * MM;
    const int b  = n0 >> 9;
    const int s0blk = n0 & (SS - 1);
    const long xrow = (long)b * LL * SS + s0blk;

    uint32_t aW0[2][4][4], aW1i[2][4][4], aW1h[2][4][4];

    // ---- init: stage weights (hi via htmp -> frags; lo persistent SMEM) ----
    stageW(Whh0, htmp, wlo0, tid);
    __syncthreads();
    loadfrags(htmp, aW0, jr, g, tg);
    __syncthreads();
    stageW(Wih1, htmp, wlo1, tid);
    __syncthreads();
    loadfrags(htmp, aW1i, jr, g, tg);
    __syncthreads();
    stageW(Whh1, htmp, wlo2, tid);
    __syncthreads();
    loadfrags(htmp, aW1h, jr, g, tg);
    __syncthreads();
    // zero all h arrays, stage x(t=0), wout
    for (int idx = tid; idx < 73728 / 4; idx += TH) ((uint32_t*)(sm + HB))[idx] = 0;
    if (tid < 16) ((float4*)xbuf)[tid] = __ldg((const float4*)(X + xrow) + tid);
    if (tid < HID) wouts[tid] = Wout[tid];

    // per-thread gate constants for unit u
    float b0c[4], w0c[4], b1c[4], bcc[4], wcc[4];
#pragma unroll
    for (int e = 0; e < 4; ++e) {
        int row = e * 64 + u;
        b0c[e] = bih0[row] + bhh0[row];
        w0c[e] = Wih0[row];
        b1c[e] = bih1[row] + bhh1[row];
        bcc[e] = bcih[row] + bchh[row];
        wcc[e] = Wcih[row];
    }
    float c0st[16], c1st[16];
#pragma unroll
    for (int i = 0; i < 16; ++i) { c0st[i] = 0.f; c1st[i] = 0.f; }
    __syncthreads();

    // ================= encoder =================
    for (int t = 0; t < LL; ++t) {
        const int p = t & 1;
        if (tid < 16 && t + 1 < LL)
            ((float4*)(xbuf + (1 - p) * 64))[tid] =
                __ldg((const float4*)(X + xrow + (long)(t + 1) * SS) + tid);

        float d[8][2][4];
#pragma unroll
        for (int nt = 0; nt < 8; ++nt)
#pragma unroll
            for (int m = 0; m < 2; ++m)
#pragma unroll
                for (int q = 0; q < 4; ++q) d[nt][m][q] = 0.f;
        // L0: Whh0 . h0_old
        matphase(aW0, wlo0, h0hi[p], h0lo[p], d, jr, g, tg);
        epilayer(d, c0st, b0c, w0c, xbuf + p * 64, h0hi[1 - p], h0lo[1 - p], u, tg);
        __syncthreads();

#pragma unroll
        for (int nt = 0; nt < 8; ++nt)
#pragma unroll
            for (int m = 0; m < 2; ++m)
#pragma unroll
                for (int q = 0; q < 4; ++q) d[nt][m][q] = 0.f;
        // L1: Wih1 . h0_new + Whh1 . h1_old
        matphase(aW1i, wlo1, h0hi[1 - p], h0lo[1 - p], d, jr, g, tg);
        matphase(aW1h, wlo2, h1hi[p], h1lo[p], d, jr, g, tg);
        epilayer(d, c1st, b1c, (const float*)0, (const float*)0,
                 h1hi[1 - p], h1lo[1 - p], u, tg);
        __syncthreads();
    }

    // ================= decoder =================
    // Stage Wchh: hi -> h0 region (unused in decoder), lo -> wlo0 slot.
    stageW(Wchh, htmp, wlo0, tid);
    __syncthreads();
    loadfrags(htmp, aW0, jr, g, tg);
    const float bo = __ldg(bout);
    __syncthreads();

    for (int dstep = 0; dstep < HOR; ++dstep) {
        const int p = dstep & 1;      // encoder left h1 final in buf0; d=0 reads 0
        float d[8][2][4];
#pragma unroll
        for (int nt = 0; nt < 8; ++nt)
#pragma unroll
            for (int m = 0; m < 2; ++m)
#pragma unroll
                for (int q = 0; q < 4; ++q) d[nt][m][q] = 0.f;
        matphase(aW0, wlo0, h1hi[p], h1lo[p], d, jr, g, tg);
        epilayer(d, c1st, bcc, wcc, xbuf + 64, h1hi[1 - p], h1lo[1 - p], u, tg);
        __syncthreads();

        if (tid < MM) {             // y = wout . h1 + bo ; feeds back as x
            const __half* hh = h1hi[1 - p] + tid * HSW;
            const __half* hl = h1lo[1 - p] + tid * HSW;
            float y = bo;
#pragma unroll 8
            for (int k = 0; k < HID; ++k)
                y = fmaf(wouts[k], __half2float(hh[k]) + __half2float(hl[k]), y);
            out[((long)(b * HOR + dstep)) * SS + s0blk + tid] = y;
            xbuf[64 + tid] = y;
        }
        __syncthreads();
    }
}

extern "C" void kernel_launch(void* const* d_in, const int* in_sizes, int n_in,
                              void* d_out, int out_size) {
    const float* X    = (const float*)d_in[0];
    const float* Wih0 = (const float*)d_in[1];
    const float* Whh0 = (const float*)d_in[2];
    const float* bih0 = (const float*)d_in[3];
    const float* bhh0 = (const float*)d_in[4];
    const float* Wih1 = (const float*)d_in[5];
    const float* Whh1 = (const float*)d_in[6];
    const float* bih1 = (const float*)d_in[7];
    const float* bhh1 = (const float*)d_in[8];
    const float* Wcih = (const float*)d_in[9];
    const float* Wchh = (const float*)d_in[10];
    const float* bcih = (const float*)d_in[11];
    const float* bchh = (const float*)d_in[12];
    const float* Wout = (const float*)d_in[13];
    const float* bout = (const float*)d_in[14];

    cudaFuncSetAttribute(lstm_mma_kernel,
                         cudaFuncAttributeMaxDynamicSharedMemorySize, SMEMB);

    lstm_mma_kernel<<<NB, TH, SMEMB>>>(
        X, Wih0, Whh0, bih0, bhh0, Wih1, Whh1, bih1, bhh1,
        Wcih, Wchh, bcih, bchh, Wout, bout, (float*)d_out);
}